// round 1
// baseline (speedup 1.0000x reference)
#include <cuda_runtime.h>
#include <cuda_fp16.h>
#include <math.h>

#define LAT 64
#define HID 256
#define NLAYERS 4
#define NBATCH 8192
#define SLOPEF 0.01f
#define TB 64      // batch rows per CTA in forward kernel
#define GROUP 8    // batch items per CTA in jacobian kernel

// Scratch (allocation-free per harness rules): bit-packed masks + per-item log|det|
__device__ unsigned g_mask[NLAYERS * NBATCH * (HID / 32)];
__device__ float g_logabs[NLAYERS * NBATCH];

// ---------------------------------------------------------------------------
// Kernel 1: forward pass (theta through 4 layers) + post-layer mask bits
// smem layout (floats):
//   W1t[64][260]  : W1t[e][h] = W1[h][e]   (transposed, padded)
//   W2t[256][68]  : W2t[h][d] = W2[d][h]   (transposed, padded)
//   aS [64][260]  : activations / h2 scratch
//   th [64][68]   : theta tile (resident across layers)
//   b1s[256], b2s[64]
// ---------------------------------------------------------------------------

__device__ __forceinline__ void gemm_h_phase(
    const float* __restrict__ th, const float* __restrict__ W1t,
    const float* __restrict__ b1s, float* __restrict__ aS,
    int ty, int tx, bool leaky)
{
    // outputs: [64 rows r][256 cols c] = th @ W1^T + b1 ; thread = 4x4 tile, 4 col-blocks
    for (int cb = 0; cb < 4; cb++) {
        const int c0 = cb * 64 + tx * 4;
        const int r0 = ty * 4;
        float acc[4][4];
        #pragma unroll
        for (int i = 0; i < 4; i++) {
            #pragma unroll
            for (int j = 0; j < 4; j++) acc[i][j] = b1s[c0 + j];
        }
        #pragma unroll 4
        for (int e = 0; e < LAT; e++) {
            float4 w = *(const float4*)&W1t[e * 260 + c0];
            #pragma unroll
            for (int i = 0; i < 4; i++) {
                float t = th[(r0 + i) * 68 + e];
                acc[i][0] += t * w.x;
                acc[i][1] += t * w.y;
                acc[i][2] += t * w.z;
                acc[i][3] += t * w.w;
            }
        }
        #pragma unroll
        for (int i = 0; i < 4; i++) {
            float4 v;
            if (leaky) {
                v.x = acc[i][0] > 0.f ? acc[i][0] : SLOPEF * acc[i][0];
                v.y = acc[i][1] > 0.f ? acc[i][1] : SLOPEF * acc[i][1];
                v.z = acc[i][2] > 0.f ? acc[i][2] : SLOPEF * acc[i][2];
                v.w = acc[i][3] > 0.f ? acc[i][3] : SLOPEF * acc[i][3];
            } else {
                v.x = acc[i][0]; v.y = acc[i][1]; v.z = acc[i][2]; v.w = acc[i][3];
            }
            *(float4*)&aS[(r0 + i) * 260 + c0] = v;
        }
    }
}

__global__ __launch_bounds__(256) void fwd_kernel(
    const float* __restrict__ z, const float* __restrict__ W1,
    const float* __restrict__ b1, const float* __restrict__ W2,
    const float* __restrict__ b2, float* __restrict__ out)
{
    extern __shared__ float s[];
    float* W1t = s;                    // 64*260
    float* W2t = W1t + 64 * 260;       // 256*68
    float* aS  = W2t + 256 * 68;       // 64*260
    float* th  = aS + 64 * 260;        // 64*68
    float* b1s = th + 64 * 68;         // 256
    float* b2s = b1s + 256;            // 64

    const int tid = threadIdx.x;
    const int ty = tid >> 4, tx = tid & 15;
    const int b0 = blockIdx.x * TB;
    const int warp = tid >> 5, lane = tid & 31;

    // load theta tile
    for (int g = tid; g < TB * LAT; g += 256) {
        int r = g >> 6, e = g & 63;
        th[r * 68 + e] = z[(b0 + r) * LAT + e];
    }
    __syncthreads();

    for (int layer = 0; layer < NLAYERS; layer++) {
        const float* W1g = W1 + layer * HID * LAT;
        const float* W2g = W2 + layer * LAT * HID;
        for (int g = tid; g < HID * LAT; g += 256) {
            int h = g >> 6, e = g & 63;
            W1t[e * 260 + h] = W1g[g];
        }
        for (int g = tid; g < LAT * HID; g += 256) {
            int d = g >> 8, h = g & 255;
            W2t[h * 68 + d] = W2g[g];
        }
        for (int g = tid; g < HID; g += 256) b1s[g] = b1[layer * HID + g];
        if (tid < LAT) b2s[tid] = b2[layer * LAT + tid];
        __syncthreads();

        // Phase A: aS = leaky(th @ W1^T + b1)
        gemm_h_phase(th, W1t, b1s, aS, ty, tx, true);
        __syncthreads();

        // Phase B: th = aS @ W2^T + b2   (64x64, thread = 4x4 tile)
        {
            const int d0 = tx * 4, r0 = ty * 4;
            float acc[4][4];
            #pragma unroll
            for (int i = 0; i < 4; i++) {
                #pragma unroll
                for (int j = 0; j < 4; j++) acc[i][j] = b2s[d0 + j];
            }
            #pragma unroll 4
            for (int h = 0; h < HID; h++) {
                float4 w = *(const float4*)&W2t[h * 68 + d0];
                #pragma unroll
                for (int i = 0; i < 4; i++) {
                    float av = aS[(r0 + i) * 260 + h];
                    acc[i][0] += av * w.x;
                    acc[i][1] += av * w.y;
                    acc[i][2] += av * w.z;
                    acc[i][3] += av * w.w;
                }
            }
            #pragma unroll
            for (int i = 0; i < 4; i++) {
                float4 v; v.x = acc[i][0]; v.y = acc[i][1]; v.z = acc[i][2]; v.w = acc[i][3];
                *(float4*)&th[(r0 + i) * 68 + d0] = v;
            }
        }
        __syncthreads();

        // Phase C: h2 = th_new @ W1^T + b1  (raw values into aS)
        gemm_h_phase(th, W1t, b1s, aS, ty, tx, false);
        __syncthreads();

        // Pack mask bits: m = (h2 > 0)
        for (int sIdx = warp; sIdx < TB * 8; sIdx += 8) {
            int r = sIdx >> 3, wi = sIdx & 7;
            unsigned bits = __ballot_sync(0xffffffffu, aS[r * 260 + wi * 32 + lane] > 0.f);
            if (lane == 0) g_mask[(layer * NBATCH + b0 + r) * 8 + wi] = bits;
        }
        __syncthreads();
    }

    // write final theta
    for (int g = tid; g < TB * LAT; g += 256) {
        int r = g >> 6, e = g & 63;
        out[(b0 + r) * LAT + e] = th[r * 68 + e];
    }
}

// ---------------------------------------------------------------------------
// Kernel 2: J_b = W2 diag(m_b) W1 (64x64), LU with partial pivoting, log|det|
// 512 threads = two 256-thread halves, each processing one item concurrently.
// ---------------------------------------------------------------------------
__global__ __launch_bounds__(512) void jac_kernel(
    const float* __restrict__ W1, const float* __restrict__ W2)
{
    extern __shared__ float s[];
    float* W2c   = s;                      // [256][68] : W2c[h][d] = W2[d][h]
    float* W1r   = W2c + 256 * 68;         // [256][68] : W1r[h][e] = W1[h][e]
    float* ms    = W1r + 256 * 68;         // [2][256]
    float* Js    = ms + 512;               // [2][64][68]
    float* pinvS = Js + 2 * 64 * 68;       // [2]
    float* colk  = pinvS + 2;              // [2][64]

    const int layer = blockIdx.y;
    const int tid = threadIdx.x;
    const int half = tid >> 8;
    const int t = tid & 255;
    const int warp = tid >> 5;
    const int lane = tid & 31;
    const bool pwarp = (warp == half * 8);   // warp 0 of each half

    const float* W1g = W1 + layer * HID * LAT;
    const float* W2g = W2 + layer * LAT * HID;
    for (int g = tid; g < HID * LAT; g += 512) {
        int d = g >> 8, h = g & 255;
        W2c[h * 68 + d] = W2g[g];
    }
    for (int g = tid; g < HID * LAT; g += 512) {
        int h = g >> 6, e = g & 63;
        W1r[h * 68 + e] = W1g[g];
    }
    __syncthreads();

    for (int it = 0; it < GROUP / 2; it++) {
        const int b = blockIdx.x * GROUP + it * 2 + half;

        // expand mask bits
        {
            unsigned w = g_mask[(layer * NBATCH + b) * 8 + (t >> 5)];
            ms[half * HID + t] = ((w >> (t & 31)) & 1u) ? 1.0f : SLOPEF;
        }
        __syncthreads();

        float* J = Js + half * 64 * 68;

        // J build: thread = 4x4 tile of [d][e]
        {
            const int ty = t >> 4, tx = t & 15;
            const int d0 = ty * 4, e0 = tx * 4;
            float acc[4][4];
            #pragma unroll
            for (int i = 0; i < 4; i++)
                #pragma unroll
                for (int j = 0; j < 4; j++) acc[i][j] = 0.f;
            const float* msl = ms + half * HID;
            #pragma unroll 4
            for (int h = 0; h < HID; h++) {
                float m = msl[h];
                float4 w2 = *(const float4*)&W2c[h * 68 + d0];
                float4 w1 = *(const float4*)&W1r[h * 68 + e0];
                float s0 = w2.x * m, s1 = w2.y * m, s2 = w2.z * m, s3 = w2.w * m;
                acc[0][0] += s0 * w1.x; acc[0][1] += s0 * w1.y; acc[0][2] += s0 * w1.z; acc[0][3] += s0 * w1.w;
                acc[1][0] += s1 * w1.x; acc[1][1] += s1 * w1.y; acc[1][2] += s1 * w1.z; acc[1][3] += s1 * w1.w;
                acc[2][0] += s2 * w1.x; acc[2][1] += s2 * w1.y; acc[2][2] += s2 * w1.z; acc[2][3] += s2 * w1.w;
                acc[3][0] += s3 * w1.x; acc[3][1] += s3 * w1.y; acc[3][2] += s3 * w1.z; acc[3][3] += s3 * w1.w;
            }
            #pragma unroll
            for (int i = 0; i < 4; i++) {
                float4 v; v.x = acc[i][0]; v.y = acc[i][1]; v.z = acc[i][2]; v.w = acc[i][3];
                *(float4*)&J[(d0 + i) * 68 + e0] = v;
            }
        }
        __syncthreads();

        // LU with partial pivoting (|det| only, so swaps need no sign tracking)
        float la = 0.f;
        for (int k = 0; k < LAT; k++) {
            if (pwarp) {
                // pivot argmax over column k, rows >= k  (lane covers r=lane, r=lane+32)
                int r1 = lane, r2 = lane + 32;
                float v1 = (r1 >= k) ? fabsf(J[r1 * 68 + k]) : -1.f;
                float v2 = (r2 >= k) ? fabsf(J[r2 * 68 + k]) : -1.f;
                float v; int pi;
                if (v2 > v1) { v = v2; pi = r2; } else { v = v1; pi = r1; }
                #pragma unroll
                for (int off = 16; off; off >>= 1) {
                    float ov = __shfl_xor_sync(0xffffffffu, v, off);
                    int oi = __shfl_xor_sync(0xffffffffu, pi, off);
                    if (ov > v) { v = ov; pi = oi; }
                }
                // swap rows k <-> pi (each lane swaps 2 columns)
                if (pi != k) {
                    float t0 = J[k * 68 + lane];
                    J[k * 68 + lane] = J[pi * 68 + lane];
                    J[pi * 68 + lane] = t0;
                    float t1 = J[k * 68 + lane + 32];
                    J[k * 68 + lane + 32] = J[pi * 68 + lane + 32];
                    J[pi * 68 + lane + 32] = t1;
                }
                __syncwarp();
                float pv = J[k * 68 + k];
                float pa = fabsf(pv);
                la += logf(fmaxf(pa, 1e-30f));
                if (lane == 0) pinvS[half] = (pa > 1e-30f) ? (1.0f / pv) : 0.0f;
                // stash column k (post-swap) so the update can overwrite it freely
                colk[half * 64 + lane] = J[lane * 68 + k];
                colk[half * 64 + lane + 32] = J[(lane + 32) * 68 + k];
            }
            __syncthreads();
            {
                // rank-1 update; full 64-col rows (cols <= k are never read again)
                const int r = t >> 2, q = t & 3;
                if (r > k) {
                    float Lr = colk[half * 64 + r] * pinvS[half];
                    const float* rowk = &J[k * 68];
                    float* rowr = &J[r * 68];
                    #pragma unroll
                    for (int c4 = 0; c4 < 4; c4++) {
                        int j = q * 16 + c4 * 4;
                        float4 u = *(const float4*)&rowk[j];
                        float4 x = *(const float4*)&rowr[j];
                        x.x -= Lr * u.x; x.y -= Lr * u.y;
                        x.z -= Lr * u.z; x.w -= Lr * u.w;
                        *(float4*)&rowr[j] = x;
                    }
                }
            }
            __syncthreads();
        }
        if (t == 0) g_logabs[layer * NBATCH + b] = la;  // t==0 is lane 0 of pwarp
        __syncthreads();
    }
}

// ---------------------------------------------------------------------------
// Kernel 3: ldj = sum_layers logsumexp(logabs.astype(f16)) with f16 emulation
// ---------------------------------------------------------------------------
__global__ __launch_bounds__(1024) void reduce_kernel(float* __restrict__ out)
{
    __shared__ float red[1024];
    const int tid = threadIdx.x;
    float ldj = 0.f;
    for (int layer = 0; layer < NLAYERS; layer++) {
        const float* la = g_logabs + layer * NBATCH;
        float mx = -1e30f;
        for (int b = tid; b < NBATCH; b += 1024) {
            float v = __half2float(__float2half(la[b]));
            mx = fmaxf(mx, v);
        }
        red[tid] = mx; __syncthreads();
        for (int s2 = 512; s2; s2 >>= 1) {
            if (tid < s2) red[tid] = fmaxf(red[tid], red[tid + s2]);
            __syncthreads();
        }
        float gmx = red[0]; __syncthreads();
        __half maxh = __float2half(gmx);
        float sum = 0.f;
        for (int b = tid; b < NBATCH; b += 1024) {
            __half xh = __float2half(la[b]);
            __half d = __hsub(xh, maxh);
            float e = expf(__half2float(d));
            sum += __half2float(__float2half(e));   // f16-rounded terms
        }
        red[tid] = sum; __syncthreads();
        for (int s2 = 512; s2; s2 >>= 1) {
            if (tid < s2) red[tid] += red[tid + s2];
            __syncthreads();
        }
        float tot = red[0]; __syncthreads();
        __half resh = __hadd(maxh, __float2half(logf(tot)));
        ldj += __half2float(resh);
    }
    if (tid == 0) out[(size_t)NBATCH * LAT] = ldj;
}

// ---------------------------------------------------------------------------
extern "C" void kernel_launch(void* const* d_in, const int* in_sizes, int n_in,
                              void* d_out, int out_size)
{
    const float* z  = (const float*)d_in[0];
    const float* W1 = (const float*)d_in[1];
    const float* b1 = (const float*)d_in[2];
    const float* W2 = (const float*)d_in[3];
    const float* b2 = (const float*)d_in[4];
    float* out = (float*)d_out;

    const size_t SM1 = (size_t)(64 * 260 + 256 * 68 + 64 * 260 + 64 * 68 + 256 + 64) * sizeof(float);
    const size_t SM2 = (size_t)(256 * 68 * 2 + 512 + 2 * 64 * 68 + 2 + 128) * sizeof(float);
    cudaFuncSetAttribute(fwd_kernel, cudaFuncAttributeMaxDynamicSharedMemorySize, (int)SM1);
    cudaFuncSetAttribute(jac_kernel, cudaFuncAttributeMaxDynamicSharedMemorySize, (int)SM2);

    fwd_kernel<<<NBATCH / TB, 256, SM1>>>(z, W1, b1, W2, b2, out);
    dim3 g2(NBATCH / GROUP, NLAYERS);
    jac_kernel<<<g2, 512, SM2>>>(W1, W2);
    reduce_kernel<<<1, 1024>>>(out);
}

// round 2
// speedup vs baseline: 1.8813x; 1.8813x over previous
#include <cuda_runtime.h>
#include <cuda_fp16.h>
#include <math.h>

#define LAT 64
#define HID 256
#define NLAYERS 4
#define NBATCH 8192
#define SLOPEF 0.01f
#define TB 64      // batch rows per CTA in forward kernel
#define G 4        // items per CTA in jacobian kernel

// Global scratch (allocation-free): masks, per-item log|det|, W2 transposed, C = W2@W1
__device__ unsigned g_mask[NLAYERS * NBATCH * (HID / 32)];
__device__ float g_logabs[NLAYERS * NBATCH];
__device__ float g_W2t[NLAYERS * HID * LAT];   // [layer][h][d]
__device__ float g_C[NLAYERS * LAT * LAT];     // [layer][d][e]

// ---------------------------------------------------------------------------
// Kernel 0: per-layer precompute: W2 transpose + C = W2 @ W1  (tiny: 4 CTAs)
// ---------------------------------------------------------------------------
__global__ void precomp_kernel(const float* __restrict__ W1,
                               const float* __restrict__ W2)
{
    extern __shared__ float ps[];          // W2s[64][257]
    float* W2s = ps;
    const int layer = blockIdx.x;
    const int t = threadIdx.x;
    const float* W1g = W1 + layer * HID * LAT;
    const float* W2g = W2 + layer * LAT * HID;

    for (int g = t; g < LAT * HID; g += 256) {
        int d = g >> 8, h = g & 255;
        W2s[d * 257 + h] = W2g[g];
    }
    __syncthreads();

    // transposed W2 to global: g_W2t[h][d]
    for (int g = t; g < HID * LAT; g += 256) {
        int h = g >> 6, d = g & 63;
        g_W2t[layer * HID * LAT + g] = W2s[d * 257 + h];
    }

    // C[d][e] = sum_h W2[d][h] * W1[h][e]
    const int ty = t >> 4, tx = t & 15;
    const int d0 = ty * 4, e0 = tx * 4;
    float acc[4][4];
    #pragma unroll
    for (int i = 0; i < 4; i++)
        #pragma unroll
        for (int j = 0; j < 4; j++) acc[i][j] = 0.f;
    for (int h = 0; h < HID; h++) {
        float4 w1 = *(const float4*)&W1g[h * LAT + e0];
        #pragma unroll
        for (int i = 0; i < 4; i++) {
            float w2 = W2s[(d0 + i) * 257 + h];
            acc[i][0] += w2 * w1.x; acc[i][1] += w2 * w1.y;
            acc[i][2] += w2 * w1.z; acc[i][3] += w2 * w1.w;
        }
    }
    #pragma unroll
    for (int i = 0; i < 4; i++) {
        float4 v; v.x = acc[i][0]; v.y = acc[i][1]; v.z = acc[i][2]; v.w = acc[i][3];
        *(float4*)&g_C[layer * LAT * LAT + (d0 + i) * LAT + e0] = v;
    }
}

// ---------------------------------------------------------------------------
// Kernel 1: forward pass (theta through 4 layers) + post-layer mask bits
// ---------------------------------------------------------------------------
__device__ __forceinline__ void gemm_h_phase(
    const float* __restrict__ th, const float* __restrict__ W1t,
    const float* __restrict__ b1s, float* __restrict__ aS,
    int ty, int tx, bool leaky)
{
    for (int cb = 0; cb < 4; cb++) {
        const int c0 = cb * 64 + tx * 4;
        const int r0 = ty * 4;
        float acc[4][4];
        #pragma unroll
        for (int i = 0; i < 4; i++) {
            #pragma unroll
            for (int j = 0; j < 4; j++) acc[i][j] = b1s[c0 + j];
        }
        #pragma unroll 4
        for (int e = 0; e < LAT; e++) {
            float4 w = *(const float4*)&W1t[e * 260 + c0];
            #pragma unroll
            for (int i = 0; i < 4; i++) {
                float t = th[(r0 + i) * 68 + e];
                acc[i][0] += t * w.x;
                acc[i][1] += t * w.y;
                acc[i][2] += t * w.z;
                acc[i][3] += t * w.w;
            }
        }
        #pragma unroll
        for (int i = 0; i < 4; i++) {
            float4 v;
            if (leaky) {
                v.x = acc[i][0] > 0.f ? acc[i][0] : SLOPEF * acc[i][0];
                v.y = acc[i][1] > 0.f ? acc[i][1] : SLOPEF * acc[i][1];
                v.z = acc[i][2] > 0.f ? acc[i][2] : SLOPEF * acc[i][2];
                v.w = acc[i][3] > 0.f ? acc[i][3] : SLOPEF * acc[i][3];
            } else {
                v.x = acc[i][0]; v.y = acc[i][1]; v.z = acc[i][2]; v.w = acc[i][3];
            }
            *(float4*)&aS[(r0 + i) * 260 + c0] = v;
        }
    }
}

__global__ __launch_bounds__(256) void fwd_kernel(
    const float* __restrict__ z, const float* __restrict__ W1,
    const float* __restrict__ b1, const float* __restrict__ W2,
    const float* __restrict__ b2, float* __restrict__ out)
{
    extern __shared__ float s[];
    float* W1t = s;                    // 64*260
    float* W2t = W1t + 64 * 260;       // 256*68
    float* aS  = W2t + 256 * 68;       // 64*260
    float* th  = aS + 64 * 260;        // 64*68
    float* b1s = th + 64 * 68;         // 256
    float* b2s = b1s + 256;            // 64

    const int tid = threadIdx.x;
    const int ty = tid >> 4, tx = tid & 15;
    const int b0 = blockIdx.x * TB;
    const int warp = tid >> 5, lane = tid & 31;

    for (int g = tid; g < TB * LAT; g += 256) {
        int r = g >> 6, e = g & 63;
        th[r * 68 + e] = z[(b0 + r) * LAT + e];
    }
    __syncthreads();

    for (int layer = 0; layer < NLAYERS; layer++) {
        const float* W1g = W1 + layer * HID * LAT;
        const float* W2g = W2 + layer * LAT * HID;
        for (int g = tid; g < HID * LAT; g += 256) {
            int h = g >> 6, e = g & 63;
            W1t[e * 260 + h] = W1g[g];
        }
        for (int g = tid; g < LAT * HID; g += 256) {
            int d = g >> 8, h = g & 255;
            W2t[h * 68 + d] = W2g[g];
        }
        for (int g = tid; g < HID; g += 256) b1s[g] = b1[layer * HID + g];
        if (tid < LAT) b2s[tid] = b2[layer * LAT + tid];
        __syncthreads();

        gemm_h_phase(th, W1t, b1s, aS, ty, tx, true);
        __syncthreads();

        {
            const int d0 = tx * 4, r0 = ty * 4;
            float acc[4][4];
            #pragma unroll
            for (int i = 0; i < 4; i++) {
                #pragma unroll
                for (int j = 0; j < 4; j++) acc[i][j] = b2s[d0 + j];
            }
            #pragma unroll 4
            for (int h = 0; h < HID; h++) {
                float4 w = *(const float4*)&W2t[h * 68 + d0];
                #pragma unroll
                for (int i = 0; i < 4; i++) {
                    float av = aS[(r0 + i) * 260 + h];
                    acc[i][0] += av * w.x;
                    acc[i][1] += av * w.y;
                    acc[i][2] += av * w.z;
                    acc[i][3] += av * w.w;
                }
            }
            #pragma unroll
            for (int i = 0; i < 4; i++) {
                float4 v; v.x = acc[i][0]; v.y = acc[i][1]; v.z = acc[i][2]; v.w = acc[i][3];
                *(float4*)&th[(r0 + i) * 68 + d0] = v;
            }
        }
        __syncthreads();

        gemm_h_phase(th, W1t, b1s, aS, ty, tx, false);
        __syncthreads();

        for (int sIdx = warp; sIdx < TB * 8; sIdx += 8) {
            int r = sIdx >> 3, wi = sIdx & 7;
            unsigned bits = __ballot_sync(0xffffffffu, aS[r * 260 + wi * 32 + lane] > 0.f);
            if (lane == 0) g_mask[(layer * NBATCH + b0 + r) * 8 + wi] = bits;
        }
        __syncthreads();
    }

    for (int g = tid; g < TB * LAT; g += 256) {
        int r = g >> 6, e = g & 63;
        out[(b0 + r) * LAT + e] = th[r * 68 + e];
    }
}

// ---------------------------------------------------------------------------
// Kernel 2 (fused): sparse J build (J = cscale*C + sscale*sum_{h in sel}) then
// warp-per-item LU with partial pivoting (no __syncthreads inside LU).
// CTA: 256 threads, G=4 items. smem ~203KB.
// ---------------------------------------------------------------------------
__global__ __launch_bounds__(256) void jac_kernel(void)
{
    extern __shared__ float s[];
    float* W2c = s;                        // [256][64]: W2c[h][d]
    float* W1r = W2c + HID * LAT;          // [256][64]: W1r[h][e]
    float* Js  = W1r + HID * LAT;          // [G][64][68]
    unsigned short* sidx = (unsigned short*)(Js + G * 64 * 68);  // [G][256]
    float* smisc = (float*)(sidx + G * 256);
    int*   s_cnt   = (int*)smisc;          // [G]
    float* s_csc   = smisc + G;            // [G]
    float* s_ssc   = smisc + 2 * G;        // [G]
    int*   s_wcnt  = (int*)(smisc + 3 * G);      // [8]
    int*   s_wcnt2 = (int*)(smisc + 3 * G + 8);  // [8]

    const int layer = blockIdx.y;
    const int tid = threadIdx.x;
    const int warp = tid >> 5;
    const int lane = tid & 31;
    const int b_base = blockIdx.x * G;

    // --- load weight tiles (coalesced float4; g_W2t already transposed) ---
    {
        const float4* W2src = (const float4*)(g_W2t + layer * HID * LAT);
        const float4* W1src = (const float4*)(g_C - g_C);  // dummy init avoided below
        (void)W1src;
        float4* W2dst = (float4*)W2c;
        for (int g = tid; g < HID * LAT / 4; g += 256) W2dst[g] = W2src[g];
    }
    // W1 natural layout is [h][e] already
    // (passed via global pointer: see kernel args workaround below)
    // -- W1 is loaded in kernel_launch via a __device__ pointer-free path:
    //    we re-read from g_W1copy staged by precomp?  Simpler: pass as arg.
    // NOTE: this kernel takes no args; W1 is staged into g_W2t area? No --
    // see jac_kernel2 below. (unused)
}

// Real jac kernel (takes W1 pointer)
__global__ __launch_bounds__(256) void jac_kernel2(const float* __restrict__ W1)
{
    extern __shared__ float s[];
    float* W2c = s;                        // [256][64]: W2c[h][d]
    float* W1r = W2c + HID * LAT;          // [256][64]: W1r[h][e]
    float* Js  = W1r + HID * LAT;          // [G][64][68]
    unsigned short* sidx = (unsigned short*)(Js + G * 64 * 68);  // [G][256]
    float* smisc = (float*)(sidx + G * 256);
    int*   s_cnt   = (int*)smisc;          // [G]
    float* s_csc   = smisc + G;            // [G]
    float* s_ssc   = smisc + 2 * G;        // [G]
    int*   s_wcnt  = (int*)(smisc + 3 * G);      // [8]
    int*   s_wcnt2 = (int*)(smisc + 3 * G + 8);  // [8]

    const int layer = blockIdx.y;
    const int tid = threadIdx.x;
    const int warp = tid >> 5;
    const int lane = tid & 31;
    const int b_base = blockIdx.x * G;

    // --- load weight tiles (coalesced float4) ---
    {
        const float4* W2src = (const float4*)(g_W2t + layer * HID * LAT);
        float4* W2dst = (float4*)W2c;
        const float4* W1src = (const float4*)(W1 + layer * HID * LAT);
        float4* W1dst = (float4*)W1r;
        for (int g = tid; g < HID * LAT / 4; g += 256) {
            W2dst[g] = W2src[g];
            W1dst[g] = W1src[g];
        }
    }

    // --- per-item mask compaction (choose smaller set; base-matrix trick) ---
    for (int g = 0; g < G; g++) {
        const int b = b_base + g;
        unsigned word = g_mask[(layer * NBATCH + b) * 8 + (tid >> 5)];
        int bit = (word >> (tid & 31)) & 1;
        unsigned bal = __ballot_sync(0xffffffffu, bit);
        if (lane == 0) s_wcnt[warp] = __popc(bal);
        __syncthreads();
        int total = 0;
        #pragma unroll
        for (int w = 0; w < 8; w++) total += s_wcnt[w];
        int modeA = (total <= 128);
        int sel = modeA ? bit : (1 - bit);
        unsigned bs = __ballot_sync(0xffffffffu, sel);
        if (lane == 0) s_wcnt2[warp] = __popc(bs);
        __syncthreads();
        int base = 0;
        for (int w = 0; w < warp; w++) base += s_wcnt2[w];
        if (sel) {
            int pos = base + __popc(bs & ((1u << lane) - 1u));
            sidx[g * 256 + pos] = (unsigned short)tid;
        }
        if (tid == 0) {
            s_cnt[g] = modeA ? total : (HID - total);
            s_csc[g] = modeA ? 0.01f : 1.0f;
            s_ssc[g] = modeA ? 0.99f : -0.99f;
        }
        __syncthreads();
    }

    // --- build J for each item: 4x4 tile per thread ---
    const int ty = tid >> 4, tx = tid & 15;
    const int d0 = ty * 4, e0 = tx * 4;
    const float* Cg = g_C + layer * LAT * LAT;

    for (int g = 0; g < G; g++) {
        const int cnt = s_cnt[g];
        const float csc = s_csc[g], ssc = s_ssc[g];
        const unsigned short* idx = sidx + g * 256;
        float acc[4][4];
        #pragma unroll
        for (int i = 0; i < 4; i++)
            #pragma unroll
            for (int j = 0; j < 4; j++) acc[i][j] = 0.f;
        #pragma unroll 2
        for (int j = 0; j < cnt; j++) {
            int h = idx[j];
            float4 w2 = *(const float4*)&W2c[h * LAT + d0];
            float4 w1 = *(const float4*)&W1r[h * LAT + e0];
            acc[0][0] += w2.x * w1.x; acc[0][1] += w2.x * w1.y; acc[0][2] += w2.x * w1.z; acc[0][3] += w2.x * w1.w;
            acc[1][0] += w2.y * w1.x; acc[1][1] += w2.y * w1.y; acc[1][2] += w2.y * w1.z; acc[1][3] += w2.y * w1.w;
            acc[2][0] += w2.z * w1.x; acc[2][1] += w2.z * w1.y; acc[2][2] += w2.z * w1.z; acc[2][3] += w2.z * w1.w;
            acc[3][0] += w2.w * w1.x; acc[3][1] += w2.w * w1.y; acc[3][2] += w2.w * w1.z; acc[3][3] += w2.w * w1.w;
        }
        float* Jw = Js + g * (64 * 68);
        #pragma unroll
        for (int i = 0; i < 4; i++) {
            float4 c4 = *(const float4*)&Cg[(d0 + i) * LAT + e0];
            float4 o;
            o.x = csc * c4.x + ssc * acc[i][0];
            o.y = csc * c4.y + ssc * acc[i][1];
            o.z = csc * c4.z + ssc * acc[i][2];
            o.w = csc * c4.w + ssc * acc[i][3];
            *(float4*)&Jw[(d0 + i) * 68 + e0] = o;
        }
    }
    __syncthreads();

    // --- warp-per-item LU with partial pivoting (warps 0..G-1) ---
    if (warp < G) {
        float* Jw = Js + warp * (64 * 68);
        const int r1 = lane, r2 = lane + 32;
        float la = 0.f;

        for (int k = 0; k < LAT; k++) {
            // pivot search over column k, rows >= k
            float a1 = (r1 >= k) ? fabsf(Jw[r1 * 68 + k]) : -1.f;
            float a2 = (r2 >= k) ? fabsf(Jw[r2 * 68 + k]) : -1.f;
            float av; int pi;
            if (a2 > a1) { av = a2; pi = r2; } else { av = a1; pi = r1; }
            #pragma unroll
            for (int off = 16; off; off >>= 1) {
                float ov = __shfl_xor_sync(0xffffffffu, av, off);
                int oi = __shfl_xor_sync(0xffffffffu, pi, off);
                if (ov > av) { av = ov; pi = oi; }
            }
            // swap rows k <-> pi (16 float4s by lanes 0..15)
            if (pi != k) {
                if (lane < 16) {
                    float4 a = *(float4*)&Jw[k * 68 + lane * 4];
                    float4 bq = *(float4*)&Jw[pi * 68 + lane * 4];
                    *(float4*)&Jw[k * 68 + lane * 4] = bq;
                    *(float4*)&Jw[pi * 68 + lane * 4] = a;
                }
            }
            __syncwarp();
            float pv = Jw[k * 68 + k];
            float pa = fabsf(pv);
            la += __logf(fmaxf(pa, 1e-38f));
            float pinv = (pa > 0.f) ? (1.0f / pv) : 0.f;

            float L1 = (r1 > k) ? Jw[r1 * 68 + k] * pinv : 0.f;
            float L2 = (r2 > k) ? Jw[r2 * 68 + k] * pinv : 0.f;
            const bool u1 = (r1 > k), u2 = (r2 > k);
            float* rowk = &Jw[k * 68];
            float* row1 = &Jw[r1 * 68];
            float* row2 = &Jw[r2 * 68];
            for (int c4 = (k >> 2); c4 < 16; c4++) {
                const int c = c4 * 4;
                float4 u = *(const float4*)&rowk[c];
                if (u1) {
                    float4 x = *(float4*)&row1[c];
                    x.x -= L1 * u.x; x.y -= L1 * u.y; x.z -= L1 * u.z; x.w -= L1 * u.w;
                    *(float4*)&row1[c] = x;
                }
                if (u2) {
                    float4 x = *(float4*)&row2[c];
                    x.x -= L2 * u.x; x.y -= L2 * u.y; x.z -= L2 * u.z; x.w -= L2 * u.w;
                    *(float4*)&row2[c] = x;
                }
            }
            __syncwarp();
        }
        if (lane == 0) g_logabs[layer * NBATCH + b_base + warp] = la;
    }
}

// ---------------------------------------------------------------------------
// Kernel 3: ldj = sum_layers logsumexp(logabs.astype(f16)) with f16 emulation
// ---------------------------------------------------------------------------
__global__ __launch_bounds__(1024) void reduce_kernel(float* __restrict__ out)
{
    __shared__ float red[1024];
    const int tid = threadIdx.x;
    float ldj = 0.f;
    for (int layer = 0; layer < NLAYERS; layer++) {
        const float* la = g_logabs + layer * NBATCH;
        float mx = -1e30f;
        for (int b = tid; b < NBATCH; b += 1024) {
            float v = __half2float(__float2half(la[b]));
            mx = fmaxf(mx, v);
        }
        red[tid] = mx; __syncthreads();
        for (int s2 = 512; s2; s2 >>= 1) {
            if (tid < s2) red[tid] = fmaxf(red[tid], red[tid + s2]);
            __syncthreads();
        }
        float gmx = red[0]; __syncthreads();
        __half maxh = __float2half(gmx);
        float sum = 0.f;
        for (int b = tid; b < NBATCH; b += 1024) {
            __half xh = __float2half(la[b]);
            __half d = __hsub(xh, maxh);
            float e = expf(__half2float(d));
            sum += __half2float(__float2half(e));
        }
        red[tid] = sum; __syncthreads();
        for (int s2 = 512; s2; s2 >>= 1) {
            if (tid < s2) red[tid] += red[tid + s2];
            __syncthreads();
        }
        float tot = red[0]; __syncthreads();
        __half resh = __hadd(maxh, __float2half(logf(tot)));
        ldj += __half2float(resh);
    }
    if (tid == 0) out[(size_t)NBATCH * LAT] = ldj;
}

// ---------------------------------------------------------------------------
extern "C" void kernel_launch(void* const* d_in, const int* in_sizes, int n_in,
                              void* d_out, int out_size)
{
    const float* z  = (const float*)d_in[0];
    const float* W1 = (const float*)d_in[1];
    const float* b1 = (const float*)d_in[2];
    const float* W2 = (const float*)d_in[3];
    const float* b2 = (const float*)d_in[4];
    float* out = (float*)d_out;

    const size_t SM0 = (size_t)(64 * 257) * sizeof(float);
    const size_t SM1 = (size_t)(64 * 260 + 256 * 68 + 64 * 260 + 64 * 68 + 256 + 64) * sizeof(float);
    const size_t SM2 = (size_t)(HID * LAT * 2 + G * 64 * 68) * sizeof(float)
                     + (size_t)(G * 256) * sizeof(unsigned short)
                     + 128;
    static int configured = -1;
    cudaFuncSetAttribute(precomp_kernel, cudaFuncAttributeMaxDynamicSharedMemorySize, (int)SM0);
    cudaFuncSetAttribute(fwd_kernel, cudaFuncAttributeMaxDynamicSharedMemorySize, (int)SM1);
    cudaFuncSetAttribute(jac_kernel2, cudaFuncAttributeMaxDynamicSharedMemorySize, (int)SM2);
    (void)configured;

    precomp_kernel<<<NLAYERS, 256, SM0>>>(W1, W2);
    fwd_kernel<<<NBATCH / TB, 256, SM1>>>(z, W1, b1, W2, b2, out);
    dim3 g2(NBATCH / G, NLAYERS);
    jac_kernel2<<<g2, 256, SM2>>>(W1);
    reduce_kernel<<<1, 1024>>>(out);
}

// round 3
// speedup vs baseline: 2.6004x; 1.3822x over previous
#include <cuda_runtime.h>
#include <cuda_fp16.h>
#include <math.h>

#define LAT 64
#define HID 256
#define NLAYERS 4
#define NBATCH 8192
#define SLOPEF 0.01f
#define TB 64
#define GB 16      // items per CTA in build kernel
#define LUW 12     // warps (= items) per CTA in LU kernel
#define NITEMS (NLAYERS * NBATCH)

// Global scratch (allocation-free): masks, logdets, transposed W2, C = W2@W1, J buffer
__device__ unsigned g_mask[NITEMS * (HID / 32)];
__device__ float g_logabs[NITEMS];
__device__ float g_W2t[NLAYERS * HID * LAT];   // [layer][h][d]
__device__ float g_C[NLAYERS * LAT * LAT];     // [layer][d][e]
__device__ float g_J[NITEMS * LAT * LAT];      // 512 MB staging for Jacobians

// ---- f32x2 helpers (Blackwell packed fp32 pipe; only reachable via PTX) ----
__device__ __forceinline__ unsigned long long pack2(float a, float b) {
    unsigned long long r;
    asm("mov.b64 %0, {%1, %2};" : "=l"(r) : "f"(a), "f"(b));
    return r;
}
__device__ __forceinline__ unsigned long long fma2(unsigned long long a,
                                                   unsigned long long b,
                                                   unsigned long long c) {
    unsigned long long d;
    asm("fma.rn.f32x2 %0, %1, %2, %3;" : "=l"(d) : "l"(a), "l"(b), "l"(c));
    return d;
}
__device__ __forceinline__ void unpack2(unsigned long long p, float& lo, float& hi) {
    asm("mov.b64 {%0, %1}, %2;" : "=f"(lo), "=f"(hi) : "l"(p));
}

// ---------------------------------------------------------------------------
// Kernel 0: per-layer precompute: W2 transpose + C = W2 @ W1
// ---------------------------------------------------------------------------
__global__ void precomp_kernel(const float* __restrict__ W1,
                               const float* __restrict__ W2)
{
    extern __shared__ float ps[];          // W2s[64][257]
    float* W2s = ps;
    const int layer = blockIdx.x;
    const int t = threadIdx.x;
    const float* W1g = W1 + layer * HID * LAT;
    const float* W2g = W2 + layer * LAT * HID;

    for (int g = t; g < LAT * HID; g += 256) {
        int d = g >> 8, h = g & 255;
        W2s[d * 257 + h] = W2g[g];
    }
    __syncthreads();

    for (int g = t; g < HID * LAT; g += 256) {
        int h = g >> 6, d = g & 63;
        g_W2t[layer * HID * LAT + g] = W2s[d * 257 + h];
    }

    const int ty = t >> 4, tx = t & 15;
    const int d0 = ty * 4, e0 = tx * 4;
    float acc[4][4];
    #pragma unroll
    for (int i = 0; i < 4; i++)
        #pragma unroll
        for (int j = 0; j < 4; j++) acc[i][j] = 0.f;
    for (int h = 0; h < HID; h++) {
        float4 w1 = *(const float4*)&W1g[h * LAT + e0];
        #pragma unroll
        for (int i = 0; i < 4; i++) {
            float w2 = W2s[(d0 + i) * 257 + h];
            acc[i][0] += w2 * w1.x; acc[i][1] += w2 * w1.y;
            acc[i][2] += w2 * w1.z; acc[i][3] += w2 * w1.w;
        }
    }
    #pragma unroll
    for (int i = 0; i < 4; i++) {
        float4 v; v.x = acc[i][0]; v.y = acc[i][1]; v.z = acc[i][2]; v.w = acc[i][3];
        *(float4*)&g_C[layer * LAT * LAT + (d0 + i) * LAT + e0] = v;
    }
}

// ---------------------------------------------------------------------------
// Kernel 1: forward pass + post-layer mask bits (unchanged from round 2)
// ---------------------------------------------------------------------------
__device__ __forceinline__ void gemm_h_phase(
    const float* __restrict__ th, const float* __restrict__ W1t,
    const float* __restrict__ b1s, float* __restrict__ aS,
    int ty, int tx, bool leaky)
{
    for (int cb = 0; cb < 4; cb++) {
        const int c0 = cb * 64 + tx * 4;
        const int r0 = ty * 4;
        float acc[4][4];
        #pragma unroll
        for (int i = 0; i < 4; i++) {
            #pragma unroll
            for (int j = 0; j < 4; j++) acc[i][j] = b1s[c0 + j];
        }
        #pragma unroll 4
        for (int e = 0; e < LAT; e++) {
            float4 w = *(const float4*)&W1t[e * 260 + c0];
            #pragma unroll
            for (int i = 0; i < 4; i++) {
                float t = th[(r0 + i) * 68 + e];
                acc[i][0] += t * w.x;
                acc[i][1] += t * w.y;
                acc[i][2] += t * w.z;
                acc[i][3] += t * w.w;
            }
        }
        #pragma unroll
        for (int i = 0; i < 4; i++) {
            float4 v;
            if (leaky) {
                v.x = acc[i][0] > 0.f ? acc[i][0] : SLOPEF * acc[i][0];
                v.y = acc[i][1] > 0.f ? acc[i][1] : SLOPEF * acc[i][1];
                v.z = acc[i][2] > 0.f ? acc[i][2] : SLOPEF * acc[i][2];
                v.w = acc[i][3] > 0.f ? acc[i][3] : SLOPEF * acc[i][3];
            } else {
                v.x = acc[i][0]; v.y = acc[i][1]; v.z = acc[i][2]; v.w = acc[i][3];
            }
            *(float4*)&aS[(r0 + i) * 260 + c0] = v;
        }
    }
}

__global__ __launch_bounds__(256) void fwd_kernel(
    const float* __restrict__ z, const float* __restrict__ W1,
    const float* __restrict__ b1, const float* __restrict__ W2,
    const float* __restrict__ b2, float* __restrict__ out)
{
    extern __shared__ float s[];
    float* W1t = s;
    float* W2t = W1t + 64 * 260;
    float* aS  = W2t + 256 * 68;
    float* th  = aS + 64 * 260;
    float* b1s = th + 64 * 68;
    float* b2s = b1s + 256;

    const int tid = threadIdx.x;
    const int ty = tid >> 4, tx = tid & 15;
    const int b0 = blockIdx.x * TB;
    const int warp = tid >> 5, lane = tid & 31;

    for (int g = tid; g < TB * LAT; g += 256) {
        int r = g >> 6, e = g & 63;
        th[r * 68 + e] = z[(b0 + r) * LAT + e];
    }
    __syncthreads();

    for (int layer = 0; layer < NLAYERS; layer++) {
        const float* W1g = W1 + layer * HID * LAT;
        const float* W2g = W2 + layer * LAT * HID;
        for (int g = tid; g < HID * LAT; g += 256) {
            int h = g >> 6, e = g & 63;
            W1t[e * 260 + h] = W1g[g];
        }
        for (int g = tid; g < LAT * HID; g += 256) {
            int d = g >> 8, h = g & 255;
            W2t[h * 68 + d] = W2g[g];
        }
        for (int g = tid; g < HID; g += 256) b1s[g] = b1[layer * HID + g];
        if (tid < LAT) b2s[tid] = b2[layer * LAT + tid];
        __syncthreads();

        gemm_h_phase(th, W1t, b1s, aS, ty, tx, true);
        __syncthreads();

        {
            const int d0 = tx * 4, r0 = ty * 4;
            float acc[4][4];
            #pragma unroll
            for (int i = 0; i < 4; i++) {
                #pragma unroll
                for (int j = 0; j < 4; j++) acc[i][j] = b2s[d0 + j];
            }
            #pragma unroll 4
            for (int h = 0; h < HID; h++) {
                float4 w = *(const float4*)&W2t[h * 68 + d0];
                #pragma unroll
                for (int i = 0; i < 4; i++) {
                    float av = aS[(r0 + i) * 260 + h];
                    acc[i][0] += av * w.x;
                    acc[i][1] += av * w.y;
                    acc[i][2] += av * w.z;
                    acc[i][3] += av * w.w;
                }
            }
            #pragma unroll
            for (int i = 0; i < 4; i++) {
                float4 v; v.x = acc[i][0]; v.y = acc[i][1]; v.z = acc[i][2]; v.w = acc[i][3];
                *(float4*)&th[(r0 + i) * 68 + d0] = v;
            }
        }
        __syncthreads();

        gemm_h_phase(th, W1t, b1s, aS, ty, tx, false);
        __syncthreads();

        for (int sIdx = warp; sIdx < TB * 8; sIdx += 8) {
            int r = sIdx >> 3, wi = sIdx & 7;
            unsigned bits = __ballot_sync(0xffffffffu, aS[r * 260 + wi * 32 + lane] > 0.f);
            if (lane == 0) g_mask[(layer * NBATCH + b0 + r) * 8 + wi] = bits;
        }
        __syncthreads();
    }

    for (int g = tid; g < TB * LAT; g += 256) {
        int r = g >> 6, e = g & 63;
        out[(b0 + r) * LAT + e] = th[r * 68 + e];
    }
}

// ---------------------------------------------------------------------------
// Kernel 2a: sparse J build with f32x2 FMAs; J -> global
// ---------------------------------------------------------------------------
__global__ __launch_bounds__(256) void build_kernel(const float* __restrict__ W1)
{
    extern __shared__ float s[];
    float* W2c = s;                        // [256][64]: [h][d]
    float* W1r = W2c + HID * LAT;          // [256][64]: [h][e]
    unsigned short* sidx = (unsigned short*)(W1r + HID * LAT);   // [GB][256]
    float* smisc = (float*)(sidx + GB * 256);
    int*   s_cnt  = (int*)smisc;           // GB
    float* s_csc  = smisc + GB;            // GB
    float* s_ssc  = smisc + 2 * GB;        // GB
    int*   s_wcnt = (int*)(smisc + 3 * GB);      // 8
    int*   s_wcnt2 = s_wcnt + 8;                 // 8

    const int layer = blockIdx.y;
    const int tid = threadIdx.x;
    const int warp = tid >> 5, lane = tid & 31;
    const int b_base = blockIdx.x * GB;

    {
        const float4* a = (const float4*)(g_W2t + layer * HID * LAT);
        const float4* b = (const float4*)(W1 + layer * HID * LAT);
        float4* da = (float4*)W2c;
        float4* db = (float4*)W1r;
        for (int g = tid; g < HID * LAT / 4; g += 256) { da[g] = a[g]; db[g] = b[g]; }
    }

    // mask compaction for all GB items (smaller-set / base-matrix trick)
    for (int g = 0; g < GB; g++) {
        int b = b_base + g;
        unsigned word = g_mask[(layer * NBATCH + b) * 8 + warp];
        int bit = (word >> lane) & 1;
        unsigned bal = __ballot_sync(0xffffffffu, bit);
        if (lane == 0) s_wcnt[warp] = __popc(bal);
        __syncthreads();
        int total = 0;
        #pragma unroll
        for (int w = 0; w < 8; w++) total += s_wcnt[w];
        int modeA = (total <= 128);
        int sel = modeA ? bit : 1 - bit;
        unsigned bs = __ballot_sync(0xffffffffu, sel);
        if (lane == 0) s_wcnt2[warp] = __popc(bs);
        __syncthreads();
        int base = 0;
        for (int w = 0; w < warp; w++) base += s_wcnt2[w];
        if (sel) sidx[g * 256 + base + __popc(bs & ((1u << lane) - 1u))] = (unsigned short)tid;
        if (tid == 0) {
            s_cnt[g] = modeA ? total : HID - total;
            s_csc[g] = modeA ? 0.01f : 1.0f;
            s_ssc[g] = modeA ? 0.99f : -0.99f;
        }
        __syncthreads();
    }

    const int ty = tid >> 4, tx = tid & 15;
    const int d0 = ty * 4, e0 = tx * 4;
    float4 creg[4];
    #pragma unroll
    for (int i = 0; i < 4; i++)
        creg[i] = *(const float4*)&g_C[layer * LAT * LAT + (d0 + i) * LAT + e0];

    for (int g = 0; g < GB; g++) {
        const int cnt = s_cnt[g];
        const float csc = s_csc[g], ssc = s_ssc[g];
        const unsigned short* idx = sidx + g * 256;
        unsigned long long acc[2][4];
        #pragma unroll
        for (int p = 0; p < 2; p++)
            #pragma unroll
            for (int j = 0; j < 4; j++) acc[p][j] = 0ull;   // bits of (0.f,0.f)

        int j = 0;
        for (; j + 2 <= cnt; j += 2) {
            int ha = idx[j], hb = idx[j + 1];
            ulonglong2 w2a = *(const ulonglong2*)&W2c[ha * 64 + d0];
            float4     w1a = *(const float4*)&W1r[ha * 64 + e0];
            ulonglong2 w2b = *(const ulonglong2*)&W2c[hb * 64 + d0];
            float4     w1b = *(const float4*)&W1r[hb * 64 + e0];
            {
                unsigned long long p0 = pack2(w1a.x, w1a.x), p1 = pack2(w1a.y, w1a.y);
                unsigned long long p2 = pack2(w1a.z, w1a.z), p3 = pack2(w1a.w, w1a.w);
                acc[0][0] = fma2(w2a.x, p0, acc[0][0]); acc[1][0] = fma2(w2a.y, p0, acc[1][0]);
                acc[0][1] = fma2(w2a.x, p1, acc[0][1]); acc[1][1] = fma2(w2a.y, p1, acc[1][1]);
                acc[0][2] = fma2(w2a.x, p2, acc[0][2]); acc[1][2] = fma2(w2a.y, p2, acc[1][2]);
                acc[0][3] = fma2(w2a.x, p3, acc[0][3]); acc[1][3] = fma2(w2a.y, p3, acc[1][3]);
            }
            {
                unsigned long long p0 = pack2(w1b.x, w1b.x), p1 = pack2(w1b.y, w1b.y);
                unsigned long long p2 = pack2(w1b.z, w1b.z), p3 = pack2(w1b.w, w1b.w);
                acc[0][0] = fma2(w2b.x, p0, acc[0][0]); acc[1][0] = fma2(w2b.y, p0, acc[1][0]);
                acc[0][1] = fma2(w2b.x, p1, acc[0][1]); acc[1][1] = fma2(w2b.y, p1, acc[1][1]);
                acc[0][2] = fma2(w2b.x, p2, acc[0][2]); acc[1][2] = fma2(w2b.y, p2, acc[1][2]);
                acc[0][3] = fma2(w2b.x, p3, acc[0][3]); acc[1][3] = fma2(w2b.y, p3, acc[1][3]);
            }
        }
        if (j < cnt) {
            int ha = idx[j];
            ulonglong2 w2a = *(const ulonglong2*)&W2c[ha * 64 + d0];
            float4     w1a = *(const float4*)&W1r[ha * 64 + e0];
            unsigned long long p0 = pack2(w1a.x, w1a.x), p1 = pack2(w1a.y, w1a.y);
            unsigned long long p2 = pack2(w1a.z, w1a.z), p3 = pack2(w1a.w, w1a.w);
            acc[0][0] = fma2(w2a.x, p0, acc[0][0]); acc[1][0] = fma2(w2a.y, p0, acc[1][0]);
            acc[0][1] = fma2(w2a.x, p1, acc[0][1]); acc[1][1] = fma2(w2a.y, p1, acc[1][1]);
            acc[0][2] = fma2(w2a.x, p2, acc[0][2]); acc[1][2] = fma2(w2a.y, p2, acc[1][2]);
            acc[0][3] = fma2(w2a.x, p3, acc[0][3]); acc[1][3] = fma2(w2a.y, p3, acc[1][3]);
        }

        // combine with C and store: acc[p][j] = pair(rows d0+2p, d0+2p+1) at col e0+j
        const size_t itbase = (size_t)(layer * NBATCH + b_base + g) * 4096;
        #pragma unroll
        for (int p = 0; p < 2; p++) {
            float lo0, hi0, lo1, hi1, lo2, hi2, lo3, hi3;
            unpack2(acc[p][0], lo0, hi0); unpack2(acc[p][1], lo1, hi1);
            unpack2(acc[p][2], lo2, hi2); unpack2(acc[p][3], lo3, hi3);
            float4 c = creg[p * 2];
            float4 o;
            o.x = csc * c.x + ssc * lo0; o.y = csc * c.y + ssc * lo1;
            o.z = csc * c.z + ssc * lo2; o.w = csc * c.w + ssc * lo3;
            *(float4*)&g_J[itbase + (d0 + p * 2) * 64 + e0] = o;
            c = creg[p * 2 + 1];
            o.x = csc * c.x + ssc * hi0; o.y = csc * c.y + ssc * hi1;
            o.z = csc * c.z + ssc * hi2; o.w = csc * c.w + ssc * hi3;
            *(float4*)&g_J[itbase + (d0 + p * 2 + 1) * 64 + e0] = o;
        }
    }
}

// ---------------------------------------------------------------------------
// Kernel 2b: warp-per-item LU with partial pivoting; 12 warps/CTA, 1 CTA/SM
// Column-k values carried in registers via extraction from previous update.
// ---------------------------------------------------------------------------
__global__ __launch_bounds__(LUW * 32) void lu_kernel(void)
{
    extern __shared__ float s[];
    const int warp = threadIdx.x >> 5, lane = threadIdx.x & 31;
    const int item = blockIdx.x * LUW + warp;
    float* Jw = s + warp * (64 * 68);
    if (item >= NITEMS) return;

    // load this item's J: lane owns rows lane and lane+32
    const float4* src = (const float4*)&g_J[(size_t)item * 4096];
    #pragma unroll 4
    for (int c4 = 0; c4 < 16; c4++) {
        *(float4*)&Jw[lane * 68 + c4 * 4] = src[lane * 16 + c4];
        *(float4*)&Jw[(lane + 32) * 68 + c4 * 4] = src[(lane + 32) * 16 + c4];
    }
    __syncwarp();

    const int r1 = lane, r2 = lane + 32;
    float a1 = Jw[r1 * 68], a2 = Jw[r2 * 68];   // column-0 values
    float la = 0.f;

    for (int k = 0; k < LAT; k++) {
        // argmax over rows >= k, carrying signed pivot value
        float av, sv; int pi;
        {
            float v1 = (r1 >= k) ? fabsf(a1) : -1.f;
            float v2 = (r2 >= k) ? fabsf(a2) : -1.f;
            if (v2 > v1) { av = v2; sv = a2; pi = r2; }
            else         { av = v1; sv = a1; pi = r1; }
            #pragma unroll
            for (int off = 16; off; off >>= 1) {
                float oav = __shfl_xor_sync(0xffffffffu, av, off);
                float osv = __shfl_xor_sync(0xffffffffu, sv, off);
                int   opi = __shfl_xor_sync(0xffffffffu, pi, off);
                if (oav > av) { av = oav; sv = osv; pi = opi; }
            }
        }
        la += __logf(fmaxf(av, 1e-38f));
        float pinv = (av > 0.f) ? (1.0f / sv) : 0.f;

        // swap rows k <-> pi in smem (cols >= k only)
        if (pi != k) {
            int c0 = k >> 2;
            if (lane >= c0 && lane < 16) {
                float4 t = *(float4*)&Jw[k * 68 + lane * 4];
                *(float4*)&Jw[k * 68 + lane * 4] = *(float4*)&Jw[pi * 68 + lane * 4];
                *(float4*)&Jw[pi * 68 + lane * 4] = t;
            }
        }
        __syncwarp();

        // multipliers from register-carried column values (k<->pi exchanged)
        float srck = (k < 32) ? a1 : a2;
        float ak = __shfl_sync(0xffffffffu, srck, k & 31);
        bool u1 = (r1 > k), u2 = (r2 > k);
        float L1 = u1 ? ((r1 == pi) ? ak : a1) * pinv : 0.f;
        float L2 = u2 ? ((r2 == pi) ? ak : a2) * pinv : 0.f;

        const int cs = (k + 1) >> 2, comp = (k + 1) & 3;
        unsigned long long nL1 = pack2(-L1, -L1), nL2 = pack2(-L2, -L2);
        if (u1 | u2) {
            for (int c4 = cs; c4 < 16; c4++) {
                ulonglong2 u = *(const ulonglong2*)&Jw[k * 68 + c4 * 4];   // broadcast
                if (u1) {
                    ulonglong2 x = *(ulonglong2*)&Jw[r1 * 68 + c4 * 4];
                    x.x = fma2(u.x, nL1, x.x); x.y = fma2(u.y, nL1, x.y);
                    *(ulonglong2*)&Jw[r1 * 68 + c4 * 4] = x;
                    if (c4 == cs) {
                        float f0, f1, f2, f3;
                        unpack2(x.x, f0, f1); unpack2(x.y, f2, f3);
                        a1 = (comp == 0) ? f0 : (comp == 1) ? f1 : (comp == 2) ? f2 : f3;
                    }
                }
                if (u2) {
                    ulonglong2 y = *(ulonglong2*)&Jw[r2 * 68 + c4 * 4];
                    y.x = fma2(u.x, nL2, y.x); y.y = fma2(u.y, nL2, y.y);
                    *(ulonglong2*)&Jw[r2 * 68 + c4 * 4] = y;
                    if (c4 == cs) {
                        float f0, f1, f2, f3;
                        unpack2(y.x, f0, f1); unpack2(y.y, f2, f3);
                        a2 = (comp == 0) ? f0 : (comp == 1) ? f1 : (comp == 2) ? f2 : f3;
                    }
                }
            }
        }
        __syncwarp();
    }
    if (lane == 0) g_logabs[item] = la;
}

// ---------------------------------------------------------------------------
// Kernel 3: ldj = sum_layers logsumexp(logabs.astype(f16)) with f16 emulation
// ---------------------------------------------------------------------------
__global__ __launch_bounds__(1024) void reduce_kernel(float* __restrict__ out)
{
    __shared__ float red[1024];
    const int tid = threadIdx.x;
    float ldj = 0.f;
    for (int layer = 0; layer < NLAYERS; layer++) {
        const float* la = g_logabs + layer * NBATCH;
        float mx = -1e30f;
        for (int b = tid; b < NBATCH; b += 1024) {
            float v = __half2float(__float2half(la[b]));
            mx = fmaxf(mx, v);
        }
        red[tid] = mx; __syncthreads();
        for (int s2 = 512; s2; s2 >>= 1) {
            if (tid < s2) red[tid] = fmaxf(red[tid], red[tid + s2]);
            __syncthreads();
        }
        float gmx = red[0]; __syncthreads();
        __half maxh = __float2half(gmx);
        float sum = 0.f;
        for (int b = tid; b < NBATCH; b += 1024) {
            __half xh = __float2half(la[b]);
            __half d = __hsub(xh, maxh);
            float e = expf(__half2float(d));
            sum += __half2float(__float2half(e));
        }
        red[tid] = sum; __syncthreads();
        for (int s2 = 512; s2; s2 >>= 1) {
            if (tid < s2) red[tid] += red[tid + s2];
            __syncthreads();
        }
        float tot = red[0]; __syncthreads();
        __half resh = __hadd(maxh, __float2half(logf(tot)));
        ldj += __half2float(resh);
    }
    if (tid == 0) out[(size_t)NBATCH * LAT] = ldj;
}

// ---------------------------------------------------------------------------
extern "C" void kernel_launch(void* const* d_in, const int* in_sizes, int n_in,
                              void* d_out, int out_size)
{
    const float* z  = (const float*)d_in[0];
    const float* W1 = (const float*)d_in[1];
    const float* b1 = (const float*)d_in[2];
    const float* W2 = (const float*)d_in[3];
    const float* b2 = (const float*)d_in[4];
    float* out = (float*)d_out;

    const size_t SM0 = (size_t)(64 * 257) * sizeof(float);
    const size_t SM1 = (size_t)(64 * 260 + 256 * 68 + 64 * 260 + 64 * 68 + 256 + 64) * sizeof(float);
    const size_t SMB = (size_t)(HID * LAT * 2) * sizeof(float)
                     + (size_t)(GB * 256) * sizeof(unsigned short)
                     + (size_t)(3 * GB + 16) * sizeof(float);
    const size_t SML = (size_t)(LUW * 64 * 68) * sizeof(float);

    cudaFuncSetAttribute(precomp_kernel, cudaFuncAttributeMaxDynamicSharedMemorySize, (int)SM0);
    cudaFuncSetAttribute(fwd_kernel, cudaFuncAttributeMaxDynamicSharedMemorySize, (int)SM1);
    cudaFuncSetAttribute(build_kernel, cudaFuncAttributeMaxDynamicSharedMemorySize, (int)SMB);
    cudaFuncSetAttribute(lu_kernel, cudaFuncAttributeMaxDynamicSharedMemorySize, (int)SML);

    precomp_kernel<<<NLAYERS, 256, SM0>>>(W1, W2);
    fwd_kernel<<<NBATCH / TB, 256, SM1>>>(z, W1, b1, W2, b2, out);
    dim3 gb(NBATCH / GB, NLAYERS);
    build_kernel<<<gb, 256, SMB>>>(W1);
    lu_kernel<<<(NITEMS + LUW - 1) / LUW, LUW * 32, SML>>>();
    reduce_kernel<<<1, 1024>>>(out);
}

// round 4
// speedup vs baseline: 3.0621x; 1.1776x over previous
#include <cuda_runtime.h>
#include <cuda_fp16.h>
#include <math.h>

#define LAT 64
#define HID 256
#define NLAYERS 4
#define NBATCH 8192
#define SLOPEF 0.01f
#define TB 64
#define GB 32      // items per CTA in build kernel (2 teams x 16)
#define LUW 8      // warps (= items) per CTA in LU kernel
#define NITEMS (NLAYERS * NBATCH)

// Global scratch (allocation-free): masks, logdets, transposed W2, C = W2@W1, J buffer
__device__ unsigned g_mask[NITEMS * (HID / 32)];
__device__ float g_logabs[NITEMS];
__device__ float g_W2t[NLAYERS * HID * LAT];   // [layer][h][d]
__device__ float g_C[NLAYERS * LAT * LAT];     // [layer][d][e]
__device__ float g_J[NITEMS * LAT * LAT];      // 512 MB staging for Jacobians

// ---- f32x2 helpers (Blackwell packed fp32 pipe; only reachable via PTX) ----
__device__ __forceinline__ unsigned long long pack2(float a, float b) {
    unsigned long long r;
    asm("mov.b64 %0, {%1, %2};" : "=l"(r) : "f"(a), "f"(b));
    return r;
}
__device__ __forceinline__ unsigned long long fma2(unsigned long long a,
                                                   unsigned long long b,
                                                   unsigned long long c) {
    unsigned long long d;
    asm("fma.rn.f32x2 %0, %1, %2, %3;" : "=l"(d) : "l"(a), "l"(b), "l"(c));
    return d;
}
__device__ __forceinline__ void unpack2(unsigned long long p, float& lo, float& hi) {
    asm("mov.b64 {%0, %1}, %2;" : "=f"(lo), "=f"(hi) : "l"(p));
}

// ---------------------------------------------------------------------------
// Kernel 0: per-layer precompute: W2 transpose + C = W2 @ W1
// ---------------------------------------------------------------------------
__global__ void precomp_kernel(const float* __restrict__ W1,
                               const float* __restrict__ W2)
{
    extern __shared__ float ps[];          // W2s[64][257]
    float* W2s = ps;
    const int layer = blockIdx.x;
    const int t = threadIdx.x;
    const float* W1g = W1 + layer * HID * LAT;
    const float* W2g = W2 + layer * LAT * HID;

    for (int g = t; g < LAT * HID; g += 256) {
        int d = g >> 8, h = g & 255;
        W2s[d * 257 + h] = W2g[g];
    }
    __syncthreads();

    for (int g = t; g < HID * LAT; g += 256) {
        int h = g >> 6, d = g & 63;
        g_W2t[layer * HID * LAT + g] = W2s[d * 257 + h];
    }

    const int ty = t >> 4, tx = t & 15;
    const int d0 = ty * 4, e0 = tx * 4;
    float acc[4][4];
    #pragma unroll
    for (int i = 0; i < 4; i++)
        #pragma unroll
        for (int j = 0; j < 4; j++) acc[i][j] = 0.f;
    for (int h = 0; h < HID; h++) {
        float4 w1 = *(const float4*)&W1g[h * LAT + e0];
        #pragma unroll
        for (int i = 0; i < 4; i++) {
            float w2 = W2s[(d0 + i) * 257 + h];
            acc[i][0] += w2 * w1.x; acc[i][1] += w2 * w1.y;
            acc[i][2] += w2 * w1.z; acc[i][3] += w2 * w1.w;
        }
    }
    #pragma unroll
    for (int i = 0; i < 4; i++) {
        float4 v; v.x = acc[i][0]; v.y = acc[i][1]; v.z = acc[i][2]; v.w = acc[i][3];
        *(float4*)&g_C[layer * LAT * LAT + (d0 + i) * LAT + e0] = v;
    }
}

// ---------------------------------------------------------------------------
// Kernel 1: forward pass + post-layer mask bits
// ---------------------------------------------------------------------------
__device__ __forceinline__ void gemm_h_phase(
    const float* __restrict__ th, const float* __restrict__ W1t,
    const float* __restrict__ b1s, float* __restrict__ aS,
    int ty, int tx, bool leaky)
{
    for (int cb = 0; cb < 4; cb++) {
        const int c0 = cb * 64 + tx * 4;
        const int r0 = ty * 4;
        float acc[4][4];
        #pragma unroll
        for (int i = 0; i < 4; i++) {
            #pragma unroll
            for (int j = 0; j < 4; j++) acc[i][j] = b1s[c0 + j];
        }
        #pragma unroll 4
        for (int e = 0; e < LAT; e++) {
            float4 w = *(const float4*)&W1t[e * 260 + c0];
            #pragma unroll
            for (int i = 0; i < 4; i++) {
                float t = th[(r0 + i) * 68 + e];
                acc[i][0] += t * w.x;
                acc[i][1] += t * w.y;
                acc[i][2] += t * w.z;
                acc[i][3] += t * w.w;
            }
        }
        #pragma unroll
        for (int i = 0; i < 4; i++) {
            float4 v;
            if (leaky) {
                v.x = acc[i][0] > 0.f ? acc[i][0] : SLOPEF * acc[i][0];
                v.y = acc[i][1] > 0.f ? acc[i][1] : SLOPEF * acc[i][1];
                v.z = acc[i][2] > 0.f ? acc[i][2] : SLOPEF * acc[i][2];
                v.w = acc[i][3] > 0.f ? acc[i][3] : SLOPEF * acc[i][3];
            } else {
                v.x = acc[i][0]; v.y = acc[i][1]; v.z = acc[i][2]; v.w = acc[i][3];
            }
            *(float4*)&aS[(r0 + i) * 260 + c0] = v;
        }
    }
}

__global__ __launch_bounds__(256) void fwd_kernel(
    const float* __restrict__ z, const float* __restrict__ W1,
    const float* __restrict__ b1, const float* __restrict__ W2,
    const float* __restrict__ b2, float* __restrict__ out)
{
    extern __shared__ float s[];
    float* W1t = s;
    float* W2t = W1t + 64 * 260;
    float* aS  = W2t + 256 * 68;
    float* th  = aS + 64 * 260;
    float* b1s = th + 64 * 68;
    float* b2s = b1s + 256;

    const int tid = threadIdx.x;
    const int ty = tid >> 4, tx = tid & 15;
    const int b0 = blockIdx.x * TB;
    const int warp = tid >> 5, lane = tid & 31;

    for (int g = tid; g < TB * LAT; g += 256) {
        int r = g >> 6, e = g & 63;
        th[r * 68 + e] = z[(b0 + r) * LAT + e];
    }
    __syncthreads();

    for (int layer = 0; layer < NLAYERS; layer++) {
        const float* W1g = W1 + layer * HID * LAT;
        const float* W2g = W2 + layer * LAT * HID;
        for (int g = tid; g < HID * LAT; g += 256) {
            int h = g >> 6, e = g & 63;
            W1t[e * 260 + h] = W1g[g];
        }
        for (int g = tid; g < LAT * HID; g += 256) {
            int d = g >> 8, h = g & 255;
            W2t[h * 68 + d] = W2g[g];
        }
        for (int g = tid; g < HID; g += 256) b1s[g] = b1[layer * HID + g];
        if (tid < LAT) b2s[tid] = b2[layer * LAT + tid];
        __syncthreads();

        gemm_h_phase(th, W1t, b1s, aS, ty, tx, true);
        __syncthreads();

        {
            const int d0 = tx * 4, r0 = ty * 4;
            float acc[4][4];
            #pragma unroll
            for (int i = 0; i < 4; i++) {
                #pragma unroll
                for (int j = 0; j < 4; j++) acc[i][j] = b2s[d0 + j];
            }
            #pragma unroll 4
            for (int h = 0; h < HID; h++) {
                float4 w = *(const float4*)&W2t[h * 68 + d0];
                #pragma unroll
                for (int i = 0; i < 4; i++) {
                    float av = aS[(r0 + i) * 260 + h];
                    acc[i][0] += av * w.x;
                    acc[i][1] += av * w.y;
                    acc[i][2] += av * w.z;
                    acc[i][3] += av * w.w;
                }
            }
            #pragma unroll
            for (int i = 0; i < 4; i++) {
                float4 v; v.x = acc[i][0]; v.y = acc[i][1]; v.z = acc[i][2]; v.w = acc[i][3];
                *(float4*)&th[(r0 + i) * 68 + d0] = v;
            }
        }
        __syncthreads();

        gemm_h_phase(th, W1t, b1s, aS, ty, tx, false);
        __syncthreads();

        for (int sIdx = warp; sIdx < TB * 8; sIdx += 8) {
            int r = sIdx >> 3, wi = sIdx & 7;
            unsigned bits = __ballot_sync(0xffffffffu, aS[r * 260 + wi * 32 + lane] > 0.f);
            if (lane == 0) g_mask[(layer * NBATCH + b0 + r) * 8 + wi] = bits;
        }
        __syncthreads();
    }

    for (int g = tid; g < TB * LAT; g += 256) {
        int r = g >> 6, e = g & 63;
        out[(b0 + r) * LAT + e] = th[r * 68 + e];
    }
}

// ---------------------------------------------------------------------------
// Kernel 2a: sparse J build, f32x2 FMAs, 512 threads = 2 teams x 16 items
// ---------------------------------------------------------------------------
__global__ __launch_bounds__(512) void build_kernel(const float* __restrict__ W1)
{
    extern __shared__ float s[];
    float* W2c = s;                        // [256][64]: [h][d]
    float* W1r = W2c + HID * LAT;          // [256][64]: [h][e]
    unsigned short* sidx = (unsigned short*)(W1r + HID * LAT);   // [GB][256]
    float* smisc = (float*)(sidx + GB * 256);
    int*   s_cnt  = (int*)smisc;           // GB
    float* s_csc  = smisc + GB;            // GB
    float* s_ssc  = smisc + 2 * GB;        // GB
    int*   s_wcnt  = (int*)(smisc + 3 * GB);    // [2][8]
    int*   s_wcnt2 = s_wcnt + 16;               // [2][8]

    const int layer = blockIdx.y;
    const int tid = threadIdx.x;
    const int team = tid >> 8;
    const int t = tid & 255;
    const int warp_t = t >> 5, lane = tid & 31;
    const int b_base = blockIdx.x * GB;

    {
        const float4* a = (const float4*)(g_W2t + layer * HID * LAT);
        const float4* b = (const float4*)(W1 + layer * HID * LAT);
        float4* da = (float4*)W2c;
        float4* db = (float4*)W1r;
        for (int g = tid; g < HID * LAT / 4; g += 512) { da[g] = a[g]; db[g] = b[g]; }
    }

    // mask compaction: each team compacts its own 16 items
    for (int gl = 0; gl < 16; gl++) {
        int gg = team * 16 + gl;
        int b = b_base + gg;
        unsigned word = g_mask[(layer * NBATCH + b) * 8 + warp_t];
        int bit = (word >> lane) & 1;
        unsigned bal = __ballot_sync(0xffffffffu, bit);
        if (lane == 0) s_wcnt[team * 8 + warp_t] = __popc(bal);
        __syncthreads();
        int total = 0;
        #pragma unroll
        for (int w = 0; w < 8; w++) total += s_wcnt[team * 8 + w];
        int modeA = (total <= 128);
        int sel = modeA ? bit : 1 - bit;
        unsigned bs = __ballot_sync(0xffffffffu, sel);
        if (lane == 0) s_wcnt2[team * 8 + warp_t] = __popc(bs);
        __syncthreads();
        int base = 0;
        for (int w = 0; w < warp_t; w++) base += s_wcnt2[team * 8 + w];
        if (sel) sidx[gg * 256 + base + __popc(bs & ((1u << lane) - 1u))] = (unsigned short)t;
        if (t == 0) {
            s_cnt[gg] = modeA ? total : HID - total;
            s_csc[gg] = modeA ? 0.01f : 1.0f;
            s_ssc[gg] = modeA ? 0.99f : -0.99f;
        }
        __syncthreads();
    }

    const int ty = t >> 4, tx = t & 15;
    const int d0 = ty * 4, e0 = tx * 4;
    float4 creg[4];
    #pragma unroll
    for (int i = 0; i < 4; i++)
        creg[i] = *(const float4*)&g_C[layer * LAT * LAT + (d0 + i) * LAT + e0];

    for (int gl = 0; gl < 16; gl++) {
        const int gg = team * 16 + gl;
        const int cnt = s_cnt[gg];
        const float csc = s_csc[gg], ssc = s_ssc[gg];
        const unsigned short* idx = sidx + gg * 256;
        unsigned long long acc[2][4];
        #pragma unroll
        for (int p = 0; p < 2; p++)
            #pragma unroll
            for (int j = 0; j < 4; j++) acc[p][j] = 0ull;

        int j = 0;
        for (; j + 2 <= cnt; j += 2) {
            int ha = idx[j], hb = idx[j + 1];
            ulonglong2 w2a = *(const ulonglong2*)&W2c[ha * 64 + d0];
            float4     w1a = *(const float4*)&W1r[ha * 64 + e0];
            ulonglong2 w2b = *(const ulonglong2*)&W2c[hb * 64 + d0];
            float4     w1b = *(const float4*)&W1r[hb * 64 + e0];
            {
                unsigned long long p0 = pack2(w1a.x, w1a.x), p1 = pack2(w1a.y, w1a.y);
                unsigned long long p2 = pack2(w1a.z, w1a.z), p3 = pack2(w1a.w, w1a.w);
                acc[0][0] = fma2(w2a.x, p0, acc[0][0]); acc[1][0] = fma2(w2a.y, p0, acc[1][0]);
                acc[0][1] = fma2(w2a.x, p1, acc[0][1]); acc[1][1] = fma2(w2a.y, p1, acc[1][1]);
                acc[0][2] = fma2(w2a.x, p2, acc[0][2]); acc[1][2] = fma2(w2a.y, p2, acc[1][2]);
                acc[0][3] = fma2(w2a.x, p3, acc[0][3]); acc[1][3] = fma2(w2a.y, p3, acc[1][3]);
            }
            {
                unsigned long long p0 = pack2(w1b.x, w1b.x), p1 = pack2(w1b.y, w1b.y);
                unsigned long long p2 = pack2(w1b.z, w1b.z), p3 = pack2(w1b.w, w1b.w);
                acc[0][0] = fma2(w2b.x, p0, acc[0][0]); acc[1][0] = fma2(w2b.y, p0, acc[1][0]);
                acc[0][1] = fma2(w2b.x, p1, acc[0][1]); acc[1][1] = fma2(w2b.y, p1, acc[1][1]);
                acc[0][2] = fma2(w2b.x, p2, acc[0][2]); acc[1][2] = fma2(w2b.y, p2, acc[1][2]);
                acc[0][3] = fma2(w2b.x, p3, acc[0][3]); acc[1][3] = fma2(w2b.y, p3, acc[1][3]);
            }
        }
        if (j < cnt) {
            int ha = idx[j];
            ulonglong2 w2a = *(const ulonglong2*)&W2c[ha * 64 + d0];
            float4     w1a = *(const float4*)&W1r[ha * 64 + e0];
            unsigned long long p0 = pack2(w1a.x, w1a.x), p1 = pack2(w1a.y, w1a.y);
            unsigned long long p2 = pack2(w1a.z, w1a.z), p3 = pack2(w1a.w, w1a.w);
            acc[0][0] = fma2(w2a.x, p0, acc[0][0]); acc[1][0] = fma2(w2a.y, p0, acc[1][0]);
            acc[0][1] = fma2(w2a.x, p1, acc[0][1]); acc[1][1] = fma2(w2a.y, p1, acc[1][1]);
            acc[0][2] = fma2(w2a.x, p2, acc[0][2]); acc[1][2] = fma2(w2a.y, p2, acc[1][2]);
            acc[0][3] = fma2(w2a.x, p3, acc[0][3]); acc[1][3] = fma2(w2a.y, p3, acc[1][3]);
        }

        const size_t itbase = (size_t)(layer * NBATCH + b_base + gg) * 4096;
        #pragma unroll
        for (int p = 0; p < 2; p++) {
            float lo0, hi0, lo1, hi1, lo2, hi2, lo3, hi3;
            unpack2(acc[p][0], lo0, hi0); unpack2(acc[p][1], lo1, hi1);
            unpack2(acc[p][2], lo2, hi2); unpack2(acc[p][3], lo3, hi3);
            float4 c = creg[p * 2];
            float4 o;
            o.x = csc * c.x + ssc * lo0; o.y = csc * c.y + ssc * lo1;
            o.z = csc * c.z + ssc * lo2; o.w = csc * c.w + ssc * lo3;
            *(float4*)&g_J[itbase + (d0 + p * 2) * 64 + e0] = o;
            c = creg[p * 2 + 1];
            o.x = csc * c.x + ssc * hi0; o.y = csc * c.y + ssc * hi1;
            o.z = csc * c.z + ssc * hi2; o.w = csc * c.w + ssc * hi3;
            *(float4*)&g_J[itbase + (d0 + p * 2 + 1) * 64 + e0] = o;
        }
    }
}

// ---------------------------------------------------------------------------
// Kernel 2b: register-resident warp-per-item LU, index pivoting (no swaps).
// Each lane owns rows lane & lane+32 as 16 ulonglong2 (f32x2 pairs) each.
// smem used only for a coalesced load-staging pass.
// ---------------------------------------------------------------------------
__global__ __launch_bounds__(LUW * 32) void lu_kernel(void)
{
    extern __shared__ float s[];
    const int warp = threadIdx.x >> 5, lane = threadIdx.x & 31;
    const int item = blockIdx.x * LUW + warp;
    float* S = s + warp * (64 * 68);

    // stage: coalesced global -> smem (padded stride 68)
    const float4* src = (const float4*)&g_J[(size_t)item * 4096];
    #pragma unroll
    for (int t = 0; t < 32; t++) {
        int i = t * 32 + lane;
        int row = i >> 4, c4 = i & 15;
        *(float4*)&S[row * 68 + c4 * 4] = src[i];
    }
    __syncwarp();

    // smem -> registers: lane owns rows lane (A1) and lane+32 (A2)
    ulonglong2 A1[16], A2[16];
    #pragma unroll
    for (int c = 0; c < 16; c++) {
        A1[c] = *(const ulonglong2*)&S[lane * 68 + c * 4];
        A2[c] = *(const ulonglong2*)&S[(lane + 32) * 68 + c * 4];
    }

    const int r1i = lane, r2i = lane + 32;
    bool act1 = true, act2 = true;
    float a1, a2, dummy;
    unpack2(A1[0].x, a1, dummy);
    unpack2(A2[0].x, a2, dummy);
    float la = 0.f;

    for (int k = 0; k < LAT; k++) {
        // packed-key argmax over active rows: key = (|a| bits & ~63) | row
        unsigned k1 = act1 ? ((__float_as_uint(fabsf(a1)) & 0xFFFFFFC0u) | (unsigned)r1i) : 0u;
        unsigned k2 = act2 ? ((__float_as_uint(fabsf(a2)) & 0xFFFFFFC0u) | (unsigned)r2i) : 0u;
        unsigned key = k1 > k2 ? k1 : k2;
        #pragma unroll
        for (int off = 16; off; off >>= 1) {
            unsigned o = __shfl_xor_sync(0xffffffffu, key, off);
            key = o > key ? o : key;
        }
        const int pi = key & 63;
        const bool hi = (pi >= 32);
        const int pl = pi & 31;

        // signed pivot value from the owner lane
        float cand = hi ? a2 : a1;
        float sv = __shfl_sync(0xffffffffu, cand, pl);
        float pa = fabsf(sv);
        la += __logf(fmaxf(pa, 1e-38f));
        float pinv = (pa > 1e-30f) ? __fdividef(1.0f, sv) : 0.f;

        // retire pivot row, compute multipliers for still-active rows
        if (pi == r1i) act1 = false;
        if (pi == r2i) act2 = false;
        float L1 = act1 ? a1 * pinv : 0.f;
        float L2 = act2 ? a2 * pinv : 0.f;
        unsigned long long nL1 = pack2(-L1, -L1), nL2 = pack2(-L2, -L2);

        const int ch = k >> 2;
        const int chn = (k + 1) >> 2, compn = (k + 1) & 3;

        #pragma unroll
        for (int c = 0; c < 16; c++) {
            if (c >= ch) {
                unsigned long long px = hi ? A2[c].x : A1[c].x;
                unsigned long long py = hi ? A2[c].y : A1[c].y;
                unsigned long long u0 = __shfl_sync(0xffffffffu, px, pl);
                unsigned long long u1 = __shfl_sync(0xffffffffu, py, pl);
                A1[c].x = fma2(u0, nL1, A1[c].x);
                A1[c].y = fma2(u1, nL1, A1[c].y);
                A2[c].x = fma2(u0, nL2, A2[c].x);
                A2[c].y = fma2(u1, nL2, A2[c].y);
                if (c == chn) {
                    float f0, f1, f2, f3;
                    unpack2(A1[c].x, f0, f1); unpack2(A1[c].y, f2, f3);
                    a1 = (compn == 0) ? f0 : (compn == 1) ? f1 : (compn == 2) ? f2 : f3;
                    unpack2(A2[c].x, f0, f1); unpack2(A2[c].y, f2, f3);
                    a2 = (compn == 0) ? f0 : (compn == 1) ? f1 : (compn == 2) ? f2 : f3;
                }
            }
        }
    }
    if (lane == 0) g_logabs[item] = la;
}

// ---------------------------------------------------------------------------
// Kernel 3: ldj = sum_layers logsumexp(logabs.astype(f16)) with f16 emulation
// ---------------------------------------------------------------------------
__global__ __launch_bounds__(1024) void reduce_kernel(float* __restrict__ out)
{
    __shared__ float red[1024];
    const int tid = threadIdx.x;
    float ldj = 0.f;
    for (int layer = 0; layer < NLAYERS; layer++) {
        const float* la = g_logabs + layer * NBATCH;
        float mx = -1e30f;
        for (int b = tid; b < NBATCH; b += 1024) {
            float v = __half2float(__float2half(la[b]));
            mx = fmaxf(mx, v);
        }
        red[tid] = mx; __syncthreads();
        for (int s2 = 512; s2; s2 >>= 1) {
            if (tid < s2) red[tid] = fmaxf(red[tid], red[tid + s2]);
            __syncthreads();
        }
        float gmx = red[0]; __syncthreads();
        __half maxh = __float2half(gmx);
        float sum = 0.f;
        for (int b = tid; b < NBATCH; b += 1024) {
            __half xh = __float2half(la[b]);
            __half d = __hsub(xh, maxh);
            float e = expf(__half2float(d));
            sum += __half2float(__float2half(e));
        }
        red[tid] = sum; __syncthreads();
        for (int s2 = 512; s2; s2 >>= 1) {
            if (tid < s2) red[tid] += red[tid + s2];
            __syncthreads();
        }
        float tot = red[0]; __syncthreads();
        __half resh = __hadd(maxh, __float2half(logf(tot)));
        ldj += __half2float(resh);
    }
    if (tid == 0) out[(size_t)NBATCH * LAT] = ldj;
}

// ---------------------------------------------------------------------------
extern "C" void kernel_launch(void* const* d_in, const int* in_sizes, int n_in,
                              void* d_out, int out_size)
{
    const float* z  = (const float*)d_in[0];
    const float* W1 = (const float*)d_in[1];
    const float* b1 = (const float*)d_in[2];
    const float* W2 = (const float*)d_in[3];
    const float* b2 = (const float*)d_in[4];
    float* out = (float*)d_out;

    const size_t SM0 = (size_t)(64 * 257) * sizeof(float);
    const size_t SM1 = (size_t)(64 * 260 + 256 * 68 + 64 * 260 + 64 * 68 + 256 + 64) * sizeof(float);
    const size_t SMB = (size_t)(HID * LAT * 2) * sizeof(float)
                     + (size_t)(GB * 256) * sizeof(unsigned short)
                     + (size_t)(3 * GB + 32) * sizeof(float);
    const size_t SML = (size_t)(LUW * 64 * 68) * sizeof(float);

    cudaFuncSetAttribute(precomp_kernel, cudaFuncAttributeMaxDynamicSharedMemorySize, (int)SM0);
    cudaFuncSetAttribute(fwd_kernel, cudaFuncAttributeMaxDynamicSharedMemorySize, (int)SM1);
    cudaFuncSetAttribute(build_kernel, cudaFuncAttributeMaxDynamicSharedMemorySize, (int)SMB);
    cudaFuncSetAttribute(lu_kernel, cudaFuncAttributeMaxDynamicSharedMemorySize, (int)SML);

    precomp_kernel<<<NLAYERS, 256, SM0>>>(W1, W2);
    fwd_kernel<<<NBATCH / TB, 256, SM1>>>(z, W1, b1, W2, b2, out);
    dim3 gb(NBATCH / GB, NLAYERS);
    build_kernel<<<gb, 512, SMB>>>(W1);
    lu_kernel<<<NITEMS / LUW, LUW * 32, SML>>>();
    reduce_kernel<<<1, 1024>>>(out);
}